// round 3
// baseline (speedup 1.0000x reference)
#include <cuda_runtime.h>
#include <math.h>

#define NIMG 8
#define CCH  3
#define HI_  512
#define WI_  512
#define HO_  2048
#define WO_  2048

// x-LUT: per (layer, out_x): {wxv0, wxv1, x0c(int bits), x1c(int bits)}
// y-LUT: per (layer, out_y): {wyv0, wyv1, row0=y0c*WI (int bits), row1=y1c*WI}
__device__ float4 g_lutx[NIMG][WO_];
__device__ float4 g_luty[NIMG][HO_];

__global__ void prep_kernel(const float* __restrict__ coor) {
    int i = blockIdx.x * blockDim.x + threadIdx.x;   // 0..2047 (both dims are 2048)
    int n = blockIdx.y;                              // layer

    float c0 = coor[n * 4 + 0];
    float c1 = coor[n * 4 + 1];
    float c2 = coor[n * 4 + 2];
    float c3 = coor[n * 4 + 3];
    float X  = (1.0f / (1.0f + expf(-c0))) * (float)WO_;
    float Y  = (1.0f / (1.0f + expf(-c1))) * (float)HO_;
    float Wb = (1.0f / (1.0f + expf(-c2))) * (float)WO_;
    float Hb = (1.0f / (1.0f + expf(-c3))) * (float)HO_;
    float a  = (float)WO_ / (Wb + 1e-8f);
    float tx = 2.0f / (float)WO_ * ((float)WO_ * 0.5f - X) * a;
    float b  = (float)HO_ / (Hb + 1e-8f);
    float ty = 2.0f / (float)HO_ * ((float)HO_ * 0.5f - Y) * b;

    // x LUT
    {
        float xsn = (2.0f * (float)i + 1.0f) / (float)WO_ - 1.0f;
        float gx  = a * xsn + tx;
        float ix  = ((gx + 1.0f) * (float)WI_ - 1.0f) * 0.5f;
        float x0f = floorf(ix);
        float wx1 = ix - x0f;
        float wx0 = 1.0f - wx1;
        int   xi0 = (int)x0f;
        int   xi1 = xi0 + 1;
        float vx0 = (xi0 >= 0 && xi0 < WI_) ? 1.0f : 0.0f;
        float vx1 = (xi1 >= 0 && xi1 < WI_) ? 1.0f : 0.0f;
        int x0c = min(max(xi0, 0), WI_ - 1);
        int x1c = min(max(xi1, 0), WI_ - 1);
        g_lutx[n][i] = make_float4(wx0 * vx0, wx1 * vx1,
                                   __int_as_float(x0c), __int_as_float(x1c));
    }
    // y LUT
    {
        float ysn = (2.0f * (float)i + 1.0f) / (float)HO_ - 1.0f;
        float gy  = b * ysn + ty;
        float iy  = ((gy + 1.0f) * (float)HI_ - 1.0f) * 0.5f;
        float y0f = floorf(iy);
        float wy1 = iy - y0f;
        float wy0 = 1.0f - wy1;
        int   yi0 = (int)y0f;
        int   yi1 = yi0 + 1;
        float vy0 = (yi0 >= 0 && yi0 < HI_) ? 1.0f : 0.0f;
        float vy1 = (yi1 >= 0 && yi1 < HI_) ? 1.0f : 0.0f;
        int y0c = min(max(yi0, 0), HI_ - 1);
        int y1c = min(max(yi1, 0), HI_ - 1);
        g_luty[n][i] = make_float4(wy0 * vy0, wy1 * vy1,
                                   __int_as_float(y0c * WI_), __int_as_float(y1c * WI_));
    }
}

// One thread = 4 consecutive output pixels of ONE channel.
// blockIdx.y = output row (y-LUT test uniform across block), blockIdx.z = channel.
__global__ __launch_bounds__(256) void composite_kernel(
    const float* __restrict__ src,   // [8,3,512,512]
    const float* __restrict__ bg,    // [1,3,2048,2048]
    float* __restrict__ out)         // [1,3,2048,2048]
{
    int c  = blockIdx.z;
    int y  = blockIdx.y;
    int xg = blockIdx.x * blockDim.x + threadIdx.x;   // float4 group, 0..511
    int x0 = xg << 2;

    int base4 = (c * HO_ + y) * (WO_ >> 2) + xg;

    float4 bgv = ((const float4*)bg)[base4];
    float acc[4] = {bgv.x, bgv.y, bgv.z, bgv.w};

#pragma unroll
    for (int n = 0; n < NIMG; ++n) {
        float4 ly = __ldg(&g_luty[n][y]);             // uniform across block
        float wyv0 = ly.x, wyv1 = ly.y;
        float sumwy = wyv0 + wyv1;
        if (sumwy == 0.0f) continue;                  // uniform skip — no divergence

        int row0 = __float_as_int(ly.z);
        int row1 = __float_as_int(ly.w);
        const float* sp = src + ((size_t)n * CCH + c) * (HI_ * WI_);

#pragma unroll
        for (int j = 0; j < 4; ++j) {
            float4 lx = __ldg(&g_lutx[n][x0 + j]);
            float wxv0 = lx.x, wxv1 = lx.y;
            float m = sumwy * (wxv0 + wxv1);
            if (m == 0.0f) continue;

            int x0c = __float_as_int(lx.z);
            int x1c = __float_as_int(lx.w);

            float v00 = __ldg(sp + row0 + x0c);
            float v10 = __ldg(sp + row1 + x0c);
            float v01 = __ldg(sp + row0 + x1c);
            float v11 = __ldg(sp + row1 + x1c);

            float r0 = v00 * wyv0 + v10 * wyv1;
            float r1 = v01 * wyv0 + v11 * wyv1;
            float samp = r0 * wxv0 + r1 * wxv1;
            // acc = acc*(1-m) + samp*m  ->  acc + m*(samp - acc): 1 sub + 1 fma
            acc[j] = fmaf(m, samp - acc[j], acc[j]);
        }
    }

    ((float4*)out)[base4] = make_float4(acc[0], acc[1], acc[2], acc[3]);
}

extern "C" void kernel_launch(void* const* d_in, const int* in_sizes, int n_in,
                              void* d_out, int out_size) {
    const float* src  = (const float*)d_in[0];   // src_img [8,3,512,512]
    const float* bg   = (const float*)d_in[1];   // bg_img  [1,3,2048,2048]
    const float* coor = (const float*)d_in[2];   // coor    [8,4]
    float*       out  = (float*)d_out;           // [1,3,2048,2048]

    // LUT prep: 2048 indices × 8 layers
    prep_kernel<<<dim3(WO_ / 256, NIMG, 1), 256>>>(coor);

    // Composite: x groups (512 / 4 / 256 = 2 blocks), y rows, channels
    dim3 grid((WO_ / 4) / 256, HO_, CCH);
    composite_kernel<<<grid, 256>>>(src, bg, out);
}

// round 4
// speedup vs baseline: 1.8801x; 1.8801x over previous
#include <cuda_runtime.h>
#include <math.h>

#define NIMG 8
#define CCH  3
#define HI_  512
#define WI_  512
#define HO_  2048
#define WO_  2048

// x-LUT: per (layer, out_x): {wxv0, wxv1, x0c(int bits), x1c(int bits)}
// y-LUT: per (layer, out_y): {wyv0, wyv1, row0=y0c*WI (int bits), row1=y1c*WI}
__device__ float4 g_lutx[NIMG][WO_];
__device__ float4 g_luty[NIMG][HO_];

__global__ void prep_kernel(const float* __restrict__ coor) {
    int i = blockIdx.x * blockDim.x + threadIdx.x;   // 0..2047 (both dims are 2048)
    int n = blockIdx.y;                              // layer

    float c0 = coor[n * 4 + 0];
    float c1 = coor[n * 4 + 1];
    float c2 = coor[n * 4 + 2];
    float c3 = coor[n * 4 + 3];
    float X  = (1.0f / (1.0f + expf(-c0))) * (float)WO_;
    float Y  = (1.0f / (1.0f + expf(-c1))) * (float)HO_;
    float Wb = (1.0f / (1.0f + expf(-c2))) * (float)WO_;
    float Hb = (1.0f / (1.0f + expf(-c3))) * (float)HO_;
    float a  = (float)WO_ / (Wb + 1e-8f);
    float tx = 2.0f / (float)WO_ * ((float)WO_ * 0.5f - X) * a;
    float b  = (float)HO_ / (Hb + 1e-8f);
    float ty = 2.0f / (float)HO_ * ((float)HO_ * 0.5f - Y) * b;

    // x LUT
    {
        float xsn = (2.0f * (float)i + 1.0f) / (float)WO_ - 1.0f;
        float gx  = a * xsn + tx;
        float ix  = ((gx + 1.0f) * (float)WI_ - 1.0f) * 0.5f;
        float x0f = floorf(ix);
        float wx1 = ix - x0f;
        float wx0 = 1.0f - wx1;
        int   xi0 = (int)x0f;
        int   xi1 = xi0 + 1;
        float vx0 = (xi0 >= 0 && xi0 < WI_) ? 1.0f : 0.0f;
        float vx1 = (xi1 >= 0 && xi1 < WI_) ? 1.0f : 0.0f;
        int x0c = min(max(xi0, 0), WI_ - 1);
        int x1c = min(max(xi1, 0), WI_ - 1);
        g_lutx[n][i] = make_float4(wx0 * vx0, wx1 * vx1,
                                   __int_as_float(x0c), __int_as_float(x1c));
    }
    // y LUT
    {
        float ysn = (2.0f * (float)i + 1.0f) / (float)HO_ - 1.0f;
        float gy  = b * ysn + ty;
        float iy  = ((gy + 1.0f) * (float)HI_ - 1.0f) * 0.5f;
        float y0f = floorf(iy);
        float wy1 = iy - y0f;
        float wy0 = 1.0f - wy1;
        int   yi0 = (int)y0f;
        int   yi1 = yi0 + 1;
        float vy0 = (yi0 >= 0 && yi0 < HI_) ? 1.0f : 0.0f;
        float vy1 = (yi1 >= 0 && yi1 < HI_) ? 1.0f : 0.0f;
        int y0c = min(max(yi0, 0), HI_ - 1);
        int y1c = min(max(yi1, 0), HI_ - 1);
        g_luty[n][i] = make_float4(wy0 * vy0, wy1 * vy1,
                                   __int_as_float(y0c * WI_), __int_as_float(y1c * WI_));
    }
}

// One thread = 4 consecutive output pixels, ALL 3 channels.
// blockIdx.y = output row -> y-LUT test is uniform across the block (no divergence),
// and each x-LUT entry / tap-address computation is amortized over 3 channels.
__global__ __launch_bounds__(256) void composite_kernel(
    const float* __restrict__ src,   // [8,3,512,512]
    const float* __restrict__ bg,    // [1,3,2048,2048]
    float* __restrict__ out)         // [1,3,2048,2048]
{
    int y  = blockIdx.y;
    int xg = blockIdx.x * blockDim.x + threadIdx.x;   // float4 group, 0..511
    int x0 = xg << 2;

    const int plane4 = (HO_ * WO_) >> 2;
    int base4 = y * (WO_ >> 2) + xg;

    const float4* bg4  = (const float4*)bg;
    float4*       out4 = (float4*)out;

    float4 b0 = bg4[base4];
    float4 b1 = bg4[base4 + plane4];
    float4 b2 = bg4[base4 + 2 * plane4];

    float acc[3][4] = {
        {b0.x, b0.y, b0.z, b0.w},
        {b1.x, b1.y, b1.z, b1.w},
        {b2.x, b2.y, b2.z, b2.w},
    };

#pragma unroll
    for (int n = 0; n < NIMG; ++n) {
        float4 ly = __ldg(&g_luty[n][y]);             // uniform across block
        float wyv0 = ly.x, wyv1 = ly.y;
        float sumwy = wyv0 + wyv1;
        if (sumwy == 0.0f) continue;                  // uniform skip — no divergence

        int row0 = __float_as_int(ly.z);
        int row1 = __float_as_int(ly.w);
        const float* s0 = src + (size_t)n * (CCH * HI_ * WI_);

#pragma unroll
        for (int j = 0; j < 4; ++j) {
            float4 lx = __ldg(&g_lutx[n][x0 + j]);
            float wxv0 = lx.x, wxv1 = lx.y;
            float m = sumwy * (wxv0 + wxv1);
            if (m == 0.0f) continue;

            int x0c = __float_as_int(lx.z);
            int x1c = __float_as_int(lx.w);
            int i00 = row0 + x0c;
            int i10 = row1 + x0c;
            int i01 = row0 + x1c;
            int i11 = row1 + x1c;

#pragma unroll
            for (int c = 0; c < CCH; ++c) {
                const float* sp = s0 + c * (HI_ * WI_);
                float v00 = __ldg(sp + i00);
                float v10 = __ldg(sp + i10);
                float v01 = __ldg(sp + i01);
                float v11 = __ldg(sp + i11);
                float r0 = v00 * wyv0 + v10 * wyv1;
                float r1 = v01 * wyv0 + v11 * wyv1;
                float samp = r0 * wxv0 + r1 * wxv1;
                // acc = acc*(1-m) + samp*m  ->  acc + m*(samp - acc)
                acc[c][j] = fmaf(m, samp - acc[c][j], acc[c][j]);
            }
        }
    }

    out4[base4]              = make_float4(acc[0][0], acc[0][1], acc[0][2], acc[0][3]);
    out4[base4 + plane4]     = make_float4(acc[1][0], acc[1][1], acc[1][2], acc[1][3]);
    out4[base4 + 2 * plane4] = make_float4(acc[2][0], acc[2][1], acc[2][2], acc[2][3]);
}

extern "C" void kernel_launch(void* const* d_in, const int* in_sizes, int n_in,
                              void* d_out, int out_size) {
    const float* src  = (const float*)d_in[0];   // src_img [8,3,512,512]
    const float* bg   = (const float*)d_in[1];   // bg_img  [1,3,2048,2048]
    const float* coor = (const float*)d_in[2];   // coor    [8,4]
    float*       out  = (float*)d_out;           // [1,3,2048,2048]

    // LUT prep: 2048 indices × 8 layers
    prep_kernel<<<dim3(WO_ / 256, NIMG, 1), 256>>>(coor);

    // Composite: 512 float4-groups per row -> 2 blocks of 256; one row per blockIdx.y
    dim3 grid((WO_ / 4) / 256, HO_, 1);
    composite_kernel<<<grid, 256>>>(src, bg, out);
}

// round 5
// speedup vs baseline: 2.3714x; 1.2613x over previous
#include <cuda_runtime.h>
#include <math.h>

#define NIMG 8
#define CCH  3
#define HI_  512
#define WI_  512
#define HO_  2048
#define WO_  2048

// x-LUT: per (layer, out_x): {wxv0, wxv1, x0c(int bits), x1c(int bits)}
// y-LUT: per (layer, out_y): {wyv0, wyv1, row0=y0c*WI (int bits), row1=y1c*WI}
__device__ float4 g_lutx[NIMG][WO_];
__device__ float4 g_luty[NIMG][HO_];

__global__ void prep_kernel(const float* __restrict__ coor) {
    int i = blockIdx.x * blockDim.x + threadIdx.x;   // 0..2047 (both dims are 2048)
    int n = blockIdx.y;                              // layer

    float c0 = coor[n * 4 + 0];
    float c1 = coor[n * 4 + 1];
    float c2 = coor[n * 4 + 2];
    float c3 = coor[n * 4 + 3];
    float X  = (1.0f / (1.0f + expf(-c0))) * (float)WO_;
    float Y  = (1.0f / (1.0f + expf(-c1))) * (float)HO_;
    float Wb = (1.0f / (1.0f + expf(-c2))) * (float)WO_;
    float Hb = (1.0f / (1.0f + expf(-c3))) * (float)HO_;
    float a  = (float)WO_ / (Wb + 1e-8f);
    float tx = 2.0f / (float)WO_ * ((float)WO_ * 0.5f - X) * a;
    float b  = (float)HO_ / (Hb + 1e-8f);
    float ty = 2.0f / (float)HO_ * ((float)HO_ * 0.5f - Y) * b;

    // x LUT
    {
        float xsn = (2.0f * (float)i + 1.0f) / (float)WO_ - 1.0f;
        float gx  = a * xsn + tx;
        float ix  = ((gx + 1.0f) * (float)WI_ - 1.0f) * 0.5f;
        float x0f = floorf(ix);
        float wx1 = ix - x0f;
        float wx0 = 1.0f - wx1;
        int   xi0 = (int)x0f;
        int   xi1 = xi0 + 1;
        float vx0 = (xi0 >= 0 && xi0 < WI_) ? 1.0f : 0.0f;
        float vx1 = (xi1 >= 0 && xi1 < WI_) ? 1.0f : 0.0f;
        int x0c = min(max(xi0, 0), WI_ - 1);
        int x1c = min(max(xi1, 0), WI_ - 1);
        g_lutx[n][i] = make_float4(wx0 * vx0, wx1 * vx1,
                                   __int_as_float(x0c), __int_as_float(x1c));
    }
    // y LUT
    {
        float ysn = (2.0f * (float)i + 1.0f) / (float)HO_ - 1.0f;
        float gy  = b * ysn + ty;
        float iy  = ((gy + 1.0f) * (float)HI_ - 1.0f) * 0.5f;
        float y0f = floorf(iy);
        float wy1 = iy - y0f;
        float wy0 = 1.0f - wy1;
        int   yi0 = (int)y0f;
        int   yi1 = yi0 + 1;
        float vy0 = (yi0 >= 0 && yi0 < HI_) ? 1.0f : 0.0f;
        float vy1 = (yi1 >= 0 && yi1 < HI_) ? 1.0f : 0.0f;
        int y0c = min(max(yi0, 0), HI_ - 1);
        int y1c = min(max(yi1, 0), HI_ - 1);
        g_luty[n][i] = make_float4(wy0 * vy0, wy1 * vy1,
                                   __int_as_float(y0c * WI_), __int_as_float(y1c * WI_));
    }
}

// Block = 1024 consecutive pixels of one output row; thread t owns pixels
// {xbase + t + 256k : k=0..3} (strided). All global accesses — bg, out, x-LUT,
// and the source taps — are then lane-consecutive and coalesce tightly.
__global__ __launch_bounds__(256) void composite_kernel(
    const float* __restrict__ src,   // [8,3,512,512]
    const float* __restrict__ bg,    // [1,3,2048,2048]
    float* __restrict__ out)         // [1,3,2048,2048]
{
    int y     = blockIdx.y;
    int xbase = blockIdx.x << 10;                 // 1024 px per block
    int t     = threadIdx.x;

    const int plane = HO_ * WO_;
    int rowoff = y * WO_ + xbase + t;             // pixel k is at rowoff + 256k

    float acc[3][4];
#pragma unroll
    for (int c = 0; c < CCH; ++c)
#pragma unroll
        for (int k = 0; k < 4; ++k)
            acc[c][k] = __ldg(bg + c * plane + rowoff + (k << 8));

#pragma unroll
    for (int n = 0; n < NIMG; ++n) {
        float4 ly = __ldg(&g_luty[n][y]);         // uniform across block
        float wyv0 = ly.x, wyv1 = ly.y;
        float sumwy = wyv0 + wyv1;
        if (sumwy == 0.0f) continue;              // uniform skip — no divergence

        int row0 = __float_as_int(ly.z);
        int row1 = __float_as_int(ly.w);
        const float* s0 = src + (size_t)n * (CCH * HI_ * WI_);

#pragma unroll
        for (int k = 0; k < 4; ++k) {
            float4 lx = __ldg(&g_lutx[n][xbase + t + (k << 8)]);   // coalesced
            float wxv0 = lx.x, wxv1 = lx.y;
            float m = sumwy * (wxv0 + wxv1);
            if (m == 0.0f) continue;

            int x0c = __float_as_int(lx.z);
            int x1c = __float_as_int(lx.w);
            int i00 = row0 + x0c;
            int i10 = row1 + x0c;
            int i01 = row0 + x1c;
            int i11 = row1 + x1c;

#pragma unroll
            for (int c = 0; c < CCH; ++c) {
                const float* sp = s0 + c * (HI_ * WI_);
                float v00 = __ldg(sp + i00);
                float v10 = __ldg(sp + i10);
                float v01 = __ldg(sp + i01);
                float v11 = __ldg(sp + i11);
                float r0 = v00 * wyv0 + v10 * wyv1;
                float r1 = v01 * wyv0 + v11 * wyv1;
                float samp = r0 * wxv0 + r1 * wxv1;
                // acc = acc*(1-m) + samp*m  ->  acc + m*(samp - acc)
                acc[c][k] = fmaf(m, samp - acc[c][k], acc[c][k]);
            }
        }
    }

#pragma unroll
    for (int c = 0; c < CCH; ++c)
#pragma unroll
        for (int k = 0; k < 4; ++k)
            out[c * plane + rowoff + (k << 8)] = acc[c][k];
}

extern "C" void kernel_launch(void* const* d_in, const int* in_sizes, int n_in,
                              void* d_out, int out_size) {
    const float* src  = (const float*)d_in[0];   // src_img [8,3,512,512]
    const float* bg   = (const float*)d_in[1];   // bg_img  [1,3,2048,2048]
    const float* coor = (const float*)d_in[2];   // coor    [8,4]
    float*       out  = (float*)d_out;           // [1,3,2048,2048]

    // LUT prep: 2048 indices × 8 layers
    prep_kernel<<<dim3(WO_ / 256, NIMG, 1), 256>>>(coor);

    // Composite: 2 blocks of 256 threads per row (1024 px each), one row per blockIdx.y
    dim3 grid(WO_ / 1024, HO_, 1);
    composite_kernel<<<grid, 256>>>(src, bg, out);
}

// round 6
// speedup vs baseline: 2.4653x; 1.0396x over previous
#include <cuda_runtime.h>
#include <math.h>

#define NIMG 8
#define CCH  3
#define HI_  512
#define WI_  512
#define HO_  2048
#define WO_  2048

// x-LUT: per (layer, out_x): {wxv0, wxv1, x0c(int bits), x1c(int bits)}
// y-LUT: per (layer, out_y): {wyv0, wyv1, row0=y0c*WI (int bits), row1=y1c*WI}
__device__ float4 g_lutx[NIMG][WO_];
__device__ float4 g_luty[NIMG][HO_];

__global__ void prep_kernel(const float* __restrict__ coor) {
    int i = blockIdx.x * blockDim.x + threadIdx.x;   // 0..2047 (both dims are 2048)
    int n = blockIdx.y;                              // layer

    float c0 = coor[n * 4 + 0];
    float c1 = coor[n * 4 + 1];
    float c2 = coor[n * 4 + 2];
    float c3 = coor[n * 4 + 3];
    float X  = (1.0f / (1.0f + expf(-c0))) * (float)WO_;
    float Y  = (1.0f / (1.0f + expf(-c1))) * (float)HO_;
    float Wb = (1.0f / (1.0f + expf(-c2))) * (float)WO_;
    float Hb = (1.0f / (1.0f + expf(-c3))) * (float)HO_;
    float a  = (float)WO_ / (Wb + 1e-8f);
    float tx = 2.0f / (float)WO_ * ((float)WO_ * 0.5f - X) * a;
    float b  = (float)HO_ / (Hb + 1e-8f);
    float ty = 2.0f / (float)HO_ * ((float)HO_ * 0.5f - Y) * b;

    // x LUT
    {
        float xsn = (2.0f * (float)i + 1.0f) / (float)WO_ - 1.0f;
        float gx  = a * xsn + tx;
        float ix  = ((gx + 1.0f) * (float)WI_ - 1.0f) * 0.5f;
        float x0f = floorf(ix);
        float wx1 = ix - x0f;
        float wx0 = 1.0f - wx1;
        int   xi0 = (int)x0f;
        int   xi1 = xi0 + 1;
        float vx0 = (xi0 >= 0 && xi0 < WI_) ? 1.0f : 0.0f;
        float vx1 = (xi1 >= 0 && xi1 < WI_) ? 1.0f : 0.0f;
        int x0c = min(max(xi0, 0), WI_ - 1);
        int x1c = min(max(xi1, 0), WI_ - 1);
        g_lutx[n][i] = make_float4(wx0 * vx0, wx1 * vx1,
                                   __int_as_float(x0c), __int_as_float(x1c));
    }
    // y LUT
    {
        float ysn = (2.0f * (float)i + 1.0f) / (float)HO_ - 1.0f;
        float gy  = b * ysn + ty;
        float iy  = ((gy + 1.0f) * (float)HI_ - 1.0f) * 0.5f;
        float y0f = floorf(iy);
        float wy1 = iy - y0f;
        float wy0 = 1.0f - wy1;
        int   yi0 = (int)y0f;
        int   yi1 = yi0 + 1;
        float vy0 = (yi0 >= 0 && yi0 < HI_) ? 1.0f : 0.0f;
        float vy1 = (yi1 >= 0 && yi1 < HI_) ? 1.0f : 0.0f;
        int y0c = min(max(yi0, 0), HI_ - 1);
        int y1c = min(max(yi1, 0), HI_ - 1);
        g_luty[n][i] = make_float4(wy0 * vy0, wy1 * vy1,
                                   __int_as_float(y0c * WI_), __int_as_float(y1c * WI_));
    }
}

// Block = 1024 consecutive x-positions of TWO adjacent output rows.
// Thread t owns x positions {xbase + t + 256k : k=0..3} in both rows.
// x-LUT loads / index math / m computation amortize over 2 rows x 3 channels.
__global__ __launch_bounds__(256) void composite_kernel(
    const float* __restrict__ src,   // [8,3,512,512]
    const float* __restrict__ bg,    // [1,3,2048,2048]
    float* __restrict__ out)         // [1,3,2048,2048]
{
    int y0    = blockIdx.y << 1;                  // rows y0, y0+1
    int xbase = blockIdx.x << 10;                 // 1024 px per block
    int t     = threadIdx.x;

    const int plane = HO_ * WO_;
    int off0 = y0 * WO_ + xbase + t;              // row 0, pixel k at off0 + 256k
    int off1 = off0 + WO_;                        // row 1

    float acc[2][3][4];
#pragma unroll
    for (int c = 0; c < CCH; ++c)
#pragma unroll
        for (int k = 0; k < 4; ++k) {
            acc[0][c][k] = __ldg(bg + c * plane + off0 + (k << 8));
            acc[1][c][k] = __ldg(bg + c * plane + off1 + (k << 8));
        }

#pragma unroll
    for (int n = 0; n < NIMG; ++n) {
        float4 lyA = __ldg(&g_luty[n][y0]);       // uniform across block
        float4 lyB = __ldg(&g_luty[n][y0 + 1]);
        float swA = lyA.x + lyA.y;
        float swB = lyB.x + lyB.y;
        if (swA == 0.0f && swB == 0.0f) continue; // uniform skip

        int rA0 = __float_as_int(lyA.z);
        int rA1 = __float_as_int(lyA.w);
        int rB0 = __float_as_int(lyB.z);
        int rB1 = __float_as_int(lyB.w);
        const float* s0 = src + (size_t)n * (CCH * HI_ * WI_);

#pragma unroll
        for (int k = 0; k < 4; ++k) {
            float4 lx = __ldg(&g_lutx[n][xbase + t + (k << 8)]);   // coalesced
            float wxv0 = lx.x, wxv1 = lx.y;
            float sumwx = wxv0 + wxv1;
            if (sumwx == 0.0f) continue;

            int x0c = __float_as_int(lx.z);
            int x1c = __float_as_int(lx.w);
            float mA = swA * sumwx;
            float mB = swB * sumwx;

            if (swA != 0.0f) {                    // uniform branch
                int i00 = rA0 + x0c, i10 = rA1 + x0c;
                int i01 = rA0 + x1c, i11 = rA1 + x1c;
#pragma unroll
                for (int c = 0; c < CCH; ++c) {
                    const float* sp = s0 + c * (HI_ * WI_);
                    float v00 = __ldg(sp + i00);
                    float v10 = __ldg(sp + i10);
                    float v01 = __ldg(sp + i01);
                    float v11 = __ldg(sp + i11);
                    float r0 = v00 * lyA.x + v10 * lyA.y;
                    float r1 = v01 * lyA.x + v11 * lyA.y;
                    float samp = r0 * wxv0 + r1 * wxv1;
                    acc[0][c][k] = fmaf(mA, samp - acc[0][c][k], acc[0][c][k]);
                }
            }
            if (swB != 0.0f) {                    // uniform branch
                int i00 = rB0 + x0c, i10 = rB1 + x0c;
                int i01 = rB0 + x1c, i11 = rB1 + x1c;
#pragma unroll
                for (int c = 0; c < CCH; ++c) {
                    const float* sp = s0 + c * (HI_ * WI_);
                    float v00 = __ldg(sp + i00);
                    float v10 = __ldg(sp + i10);
                    float v01 = __ldg(sp + i01);
                    float v11 = __ldg(sp + i11);
                    float r0 = v00 * lyB.x + v10 * lyB.y;
                    float r1 = v01 * lyB.x + v11 * lyB.y;
                    float samp = r0 * wxv0 + r1 * wxv1;
                    acc[1][c][k] = fmaf(mB, samp - acc[1][c][k], acc[1][c][k]);
                }
            }
        }
    }

#pragma unroll
    for (int c = 0; c < CCH; ++c)
#pragma unroll
        for (int k = 0; k < 4; ++k) {
            out[c * plane + off0 + (k << 8)] = acc[0][c][k];
            out[c * plane + off1 + (k << 8)] = acc[1][c][k];
        }
}

extern "C" void kernel_launch(void* const* d_in, const int* in_sizes, int n_in,
                              void* d_out, int out_size) {
    const float* src  = (const float*)d_in[0];   // src_img [8,3,512,512]
    const float* bg   = (const float*)d_in[1];   // bg_img  [1,3,2048,2048]
    const float* coor = (const float*)d_in[2];   // coor    [8,4]
    float*       out  = (float*)d_out;           // [1,3,2048,2048]

    // LUT prep: 2048 indices × 8 layers
    prep_kernel<<<dim3(WO_ / 256, NIMG, 1), 256>>>(coor);

    // Composite: 2 blocks of 256 threads per row-pair; 1024 row-pairs
    dim3 grid(WO_ / 1024, HO_ / 2, 1);
    composite_kernel<<<grid, 256>>>(src, bg, out);
}

// round 7
// speedup vs baseline: 2.4931x; 1.0113x over previous
#include <cuda_runtime.h>
#include <math.h>

#define NIMG 8
#define CCH  3
#define HI_  512
#define WI_  512
#define HO_  2048
#define WO_  2048

// x-LUT: per (layer, out_x): {wxv0, wxv1, x0c(int bits), x1c(int bits)}
// y-LUT: per (layer, out_y): {wyv0, wyv1, row0=y0c*WI (int bits), row1=y1c*WI}
__device__ float4 g_lutx[NIMG][WO_];
__device__ float4 g_luty[NIMG][HO_];

__global__ void prep_kernel(const float* __restrict__ coor) {
    int i = blockIdx.x * blockDim.x + threadIdx.x;   // 0..2047 (both dims are 2048)
    int n = blockIdx.y;                              // layer

    float c0 = coor[n * 4 + 0];
    float c1 = coor[n * 4 + 1];
    float c2 = coor[n * 4 + 2];
    float c3 = coor[n * 4 + 3];
    float X  = (1.0f / (1.0f + expf(-c0))) * (float)WO_;
    float Y  = (1.0f / (1.0f + expf(-c1))) * (float)HO_;
    float Wb = (1.0f / (1.0f + expf(-c2))) * (float)WO_;
    float Hb = (1.0f / (1.0f + expf(-c3))) * (float)HO_;
    float a  = (float)WO_ / (Wb + 1e-8f);
    float tx = 2.0f / (float)WO_ * ((float)WO_ * 0.5f - X) * a;
    float b  = (float)HO_ / (Hb + 1e-8f);
    float ty = 2.0f / (float)HO_ * ((float)HO_ * 0.5f - Y) * b;

    // x LUT
    {
        float xsn = (2.0f * (float)i + 1.0f) / (float)WO_ - 1.0f;
        float gx  = a * xsn + tx;
        float ix  = ((gx + 1.0f) * (float)WI_ - 1.0f) * 0.5f;
        float x0f = floorf(ix);
        float wx1 = ix - x0f;
        float wx0 = 1.0f - wx1;
        int   xi0 = (int)x0f;
        int   xi1 = xi0 + 1;
        float vx0 = (xi0 >= 0 && xi0 < WI_) ? 1.0f : 0.0f;
        float vx1 = (xi1 >= 0 && xi1 < WI_) ? 1.0f : 0.0f;
        int x0c = min(max(xi0, 0), WI_ - 1);
        int x1c = min(max(xi1, 0), WI_ - 1);
        g_lutx[n][i] = make_float4(wx0 * vx0, wx1 * vx1,
                                   __int_as_float(x0c), __int_as_float(x1c));
    }
    // y LUT
    {
        float ysn = (2.0f * (float)i + 1.0f) / (float)HO_ - 1.0f;
        float gy  = b * ysn + ty;
        float iy  = ((gy + 1.0f) * (float)HI_ - 1.0f) * 0.5f;
        float y0f = floorf(iy);
        float wy1 = iy - y0f;
        float wy0 = 1.0f - wy1;
        int   yi0 = (int)y0f;
        int   yi1 = yi0 + 1;
        float vy0 = (yi0 >= 0 && yi0 < HI_) ? 1.0f : 0.0f;
        float vy1 = (yi1 >= 0 && yi1 < HI_) ? 1.0f : 0.0f;
        int y0c = min(max(yi0, 0), HI_ - 1);
        int y1c = min(max(yi1, 0), HI_ - 1);
        g_luty[n][i] = make_float4(wy0 * vy0, wy1 * vy1,
                                   __int_as_float(y0c * WI_), __int_as_float(y1c * WI_));
    }
}

// Block = 512 consecutive x-positions of TWO adjacent output rows.
// Thread t owns x positions {xbase + t, xbase + t + 256} in both rows.
// x-LUT loads / index math amortize over 2 rows x 3 channels; small acc
// footprint keeps registers ~48 so occupancy stays high.
__global__ __launch_bounds__(256) void composite_kernel(
    const float* __restrict__ src,   // [8,3,512,512]
    const float* __restrict__ bg,    // [1,3,2048,2048]
    float* __restrict__ out)         // [1,3,2048,2048]
{
    int y0    = blockIdx.y << 1;                  // rows y0, y0+1
    int xbase = blockIdx.x << 9;                  // 512 px per block
    int t     = threadIdx.x;

    const int plane = HO_ * WO_;
    int off0 = y0 * WO_ + xbase + t;              // row 0, chunk k at off0 + 256k
    int off1 = off0 + WO_;                        // row 1

    float acc[2][3][2];
#pragma unroll
    for (int c = 0; c < CCH; ++c)
#pragma unroll
        for (int k = 0; k < 2; ++k) {
            acc[0][c][k] = __ldg(bg + c * plane + off0 + (k << 8));
            acc[1][c][k] = __ldg(bg + c * plane + off1 + (k << 8));
        }

#pragma unroll
    for (int n = 0; n < NIMG; ++n) {
        float4 lyA = __ldg(&g_luty[n][y0]);       // uniform across block
        float4 lyB = __ldg(&g_luty[n][y0 + 1]);
        float swA = lyA.x + lyA.y;
        float swB = lyB.x + lyB.y;
        if (swA == 0.0f && swB == 0.0f) continue; // uniform skip

        int rA0 = __float_as_int(lyA.z);
        int rA1 = __float_as_int(lyA.w);
        int rB0 = __float_as_int(lyB.z);
        int rB1 = __float_as_int(lyB.w);
        const float* s0 = src + (size_t)n * (CCH * HI_ * WI_);

#pragma unroll
        for (int k = 0; k < 2; ++k) {
            float4 lx = __ldg(&g_lutx[n][xbase + t + (k << 8)]);   // coalesced
            float wxv0 = lx.x, wxv1 = lx.y;
            float sumwx = wxv0 + wxv1;
            if (sumwx == 0.0f) continue;

            int x0c = __float_as_int(lx.z);
            int x1c = __float_as_int(lx.w);
            float mA = swA * sumwx;
            float mB = swB * sumwx;

            if (swA != 0.0f) {                    // uniform branch
                int i00 = rA0 + x0c, i10 = rA1 + x0c;
                int i01 = rA0 + x1c, i11 = rA1 + x1c;
#pragma unroll
                for (int c = 0; c < CCH; ++c) {
                    const float* sp = s0 + c * (HI_ * WI_);
                    float v00 = __ldg(sp + i00);
                    float v10 = __ldg(sp + i10);
                    float v01 = __ldg(sp + i01);
                    float v11 = __ldg(sp + i11);
                    float r0 = v00 * lyA.x + v10 * lyA.y;
                    float r1 = v01 * lyA.x + v11 * lyA.y;
                    float samp = r0 * wxv0 + r1 * wxv1;
                    acc[0][c][k] = fmaf(mA, samp - acc[0][c][k], acc[0][c][k]);
                }
            }
            if (swB != 0.0f) {                    // uniform branch
                int i00 = rB0 + x0c, i10 = rB1 + x0c;
                int i01 = rB0 + x1c, i11 = rB1 + x1c;
#pragma unroll
                for (int c = 0; c < CCH; ++c) {
                    const float* sp = s0 + c * (HI_ * WI_);
                    float v00 = __ldg(sp + i00);
                    float v10 = __ldg(sp + i10);
                    float v01 = __ldg(sp + i01);
                    float v11 = __ldg(sp + i11);
                    float r0 = v00 * lyB.x + v10 * lyB.y;
                    float r1 = v01 * lyB.x + v11 * lyB.y;
                    float samp = r0 * wxv0 + r1 * wxv1;
                    acc[1][c][k] = fmaf(mB, samp - acc[1][c][k], acc[1][c][k]);
                }
            }
        }
    }

#pragma unroll
    for (int c = 0; c < CCH; ++c)
#pragma unroll
        for (int k = 0; k < 2; ++k) {
            out[c * plane + off0 + (k << 8)] = acc[0][c][k];
            out[c * plane + off1 + (k << 8)] = acc[1][c][k];
        }
}

extern "C" void kernel_launch(void* const* d_in, const int* in_sizes, int n_in,
                              void* d_out, int out_size) {
    const float* src  = (const float*)d_in[0];   // src_img [8,3,512,512]
    const float* bg   = (const float*)d_in[1];   // bg_img  [1,3,2048,2048]
    const float* coor = (const float*)d_in[2];   // coor    [8,4]
    float*       out  = (float*)d_out;           // [1,3,2048,2048]

    // LUT prep: 2048 indices × 8 layers
    prep_kernel<<<dim3(WO_ / 256, NIMG, 1), 256>>>(coor);

    // Composite: 4 blocks of 256 threads per row-pair; 1024 row-pairs
    dim3 grid(WO_ / 512, HO_ / 2, 1);
    composite_kernel<<<grid, 256>>>(src, bg, out);
}

// round 8
// speedup vs baseline: 3.6484x; 1.4634x over previous
#include <cuda_runtime.h>
#include <math.h>

#define NIMG 8
#define CCH  3
#define HI_  512
#define WI_  512
#define HO_  2048
#define WO_  2048

// x-LUT: per (layer, out_x): {wxv0, wxv1, x0c(int bits), x1c(int bits)}
// y-LUT: per (layer, out_y): {wyv0, wyv1, row0=y0c*WI (int bits), row1=y1c*WI}
__device__ float4 g_lutx[NIMG][WO_];
__device__ float4 g_luty[NIMG][HO_];

__global__ void prep_kernel(const float* __restrict__ coor) {
    int i = blockIdx.x * blockDim.x + threadIdx.x;   // 0..2047 (both dims are 2048)
    int n = blockIdx.y;                              // layer

    float c0 = coor[n * 4 + 0];
    float c1 = coor[n * 4 + 1];
    float c2 = coor[n * 4 + 2];
    float c3 = coor[n * 4 + 3];
    float X  = (1.0f / (1.0f + expf(-c0))) * (float)WO_;
    float Y  = (1.0f / (1.0f + expf(-c1))) * (float)HO_;
    float Wb = (1.0f / (1.0f + expf(-c2))) * (float)WO_;
    float Hb = (1.0f / (1.0f + expf(-c3))) * (float)HO_;
    float a  = (float)WO_ / (Wb + 1e-8f);
    float tx = 2.0f / (float)WO_ * ((float)WO_ * 0.5f - X) * a;
    float b  = (float)HO_ / (Hb + 1e-8f);
    float ty = 2.0f / (float)HO_ * ((float)HO_ * 0.5f - Y) * b;

    // x LUT
    {
        float xsn = (2.0f * (float)i + 1.0f) / (float)WO_ - 1.0f;
        float gx  = a * xsn + tx;
        float ix  = ((gx + 1.0f) * (float)WI_ - 1.0f) * 0.5f;
        float x0f = floorf(ix);
        float wx1 = ix - x0f;
        float wx0 = 1.0f - wx1;
        int   xi0 = (int)x0f;
        int   xi1 = xi0 + 1;
        float vx0 = (xi0 >= 0 && xi0 < WI_) ? 1.0f : 0.0f;
        float vx1 = (xi1 >= 0 && xi1 < WI_) ? 1.0f : 0.0f;
        int x0c = min(max(xi0, 0), WI_ - 1);
        int x1c = min(max(xi1, 0), WI_ - 1);
        g_lutx[n][i] = make_float4(wx0 * vx0, wx1 * vx1,
                                   __int_as_float(x0c), __int_as_float(x1c));
    }
    // y LUT
    {
        float ysn = (2.0f * (float)i + 1.0f) / (float)HO_ - 1.0f;
        float gy  = b * ysn + ty;
        float iy  = ((gy + 1.0f) * (float)HI_ - 1.0f) * 0.5f;
        float y0f = floorf(iy);
        float wy1 = iy - y0f;
        float wy0 = 1.0f - wy1;
        int   yi0 = (int)y0f;
        int   yi1 = yi0 + 1;
        float vy0 = (yi0 >= 0 && yi0 < HI_) ? 1.0f : 0.0f;
        float vy1 = (yi1 >= 0 && yi1 < HI_) ? 1.0f : 0.0f;
        int y0c = min(max(yi0, 0), HI_ - 1);
        int y1c = min(max(yi1, 0), HI_ - 1);
        g_luty[n][i] = make_float4(wy0 * vy0, wy1 * vy1,
                                   __int_as_float(y0c * WI_), __int_as_float(y1c * WI_));
    }
}

// Front-to-back compositing: iterate layers n=7..0 (topmost first), tracking
// per-pixel transmittance T = prod(1-m). Box interiors give m==1 exactly ->
// T==0 -> deeper layers and even the bg load are skipped. Warp-uniform break
// once every pixel in the warp is fully covered.
// Block = 512 consecutive x of TWO adjacent rows; thread t owns
// {xbase+t, xbase+t+256} in both rows.
__global__ __launch_bounds__(256) void composite_kernel(
    const float* __restrict__ src,   // [8,3,512,512]
    const float* __restrict__ bg,    // [1,3,2048,2048]
    float* __restrict__ out)         // [1,3,2048,2048]
{
    int y0    = blockIdx.y << 1;                  // rows y0, y0+1
    int xbase = blockIdx.x << 9;                  // 512 px per block
    int t     = threadIdx.x;

    const int plane = HO_ * WO_;
    int off0 = y0 * WO_ + xbase + t;              // row 0, chunk k at off0 + 256k
    int off1 = off0 + WO_;                        // row 1

    float C[2][3][2];                             // accumulated premultiplied color
    float T[2][2];                                // transmittance per pixel
#pragma unroll
    for (int r = 0; r < 2; ++r)
#pragma unroll
        for (int k = 0; k < 2; ++k) {
            T[r][k] = 1.0f;
#pragma unroll
            for (int c = 0; c < CCH; ++c) C[r][c][k] = 0.0f;
        }

#pragma unroll
    for (int n = NIMG - 1; n >= 0; --n) {         // front-to-back
        // warp-wide occlusion break
        float tsum = T[0][0] + T[0][1] + T[1][0] + T[1][1];
        if (__all_sync(0xffffffffu, tsum == 0.0f)) break;

        float4 lyA = __ldg(&g_luty[n][y0]);       // uniform across block
        float4 lyB = __ldg(&g_luty[n][y0 + 1]);
        float swA = lyA.x + lyA.y;
        float swB = lyB.x + lyB.y;
        if (swA == 0.0f && swB == 0.0f) continue; // uniform skip

        int rA0 = __float_as_int(lyA.z);
        int rA1 = __float_as_int(lyA.w);
        int rB0 = __float_as_int(lyB.z);
        int rB1 = __float_as_int(lyB.w);
        const float* s0 = src + (size_t)n * (CCH * HI_ * WI_);

#pragma unroll
        for (int k = 0; k < 2; ++k) {
            float4 lx = __ldg(&g_lutx[n][xbase + t + (k << 8)]);   // coalesced
            float wxv0 = lx.x, wxv1 = lx.y;
            float sumwx = wxv0 + wxv1;
            if (sumwx == 0.0f) continue;

            int x0c = __float_as_int(lx.z);
            int x1c = __float_as_int(lx.w);

            if (swA != 0.0f && T[0][k] != 0.0f) {
                float m = swA * sumwx;
                float f = T[0][k] * m;
                int i00 = rA0 + x0c, i10 = rA1 + x0c;
                int i01 = rA0 + x1c, i11 = rA1 + x1c;
#pragma unroll
                for (int c = 0; c < CCH; ++c) {
                    const float* sp = s0 + c * (HI_ * WI_);
                    float v00 = __ldg(sp + i00);
                    float v10 = __ldg(sp + i10);
                    float v01 = __ldg(sp + i01);
                    float v11 = __ldg(sp + i11);
                    float r0 = v00 * lyA.x + v10 * lyA.y;
                    float r1 = v01 * lyA.x + v11 * lyA.y;
                    float samp = r0 * wxv0 + r1 * wxv1;
                    C[0][c][k] = fmaf(f, samp, C[0][c][k]);
                }
                T[0][k] *= (1.0f - m);
            }
            if (swB != 0.0f && T[1][k] != 0.0f) {
                float m = swB * sumwx;
                float f = T[1][k] * m;
                int i00 = rB0 + x0c, i10 = rB1 + x0c;
                int i01 = rB0 + x1c, i11 = rB1 + x1c;
#pragma unroll
                for (int c = 0; c < CCH; ++c) {
                    const float* sp = s0 + c * (HI_ * WI_);
                    float v00 = __ldg(sp + i00);
                    float v10 = __ldg(sp + i10);
                    float v01 = __ldg(sp + i01);
                    float v11 = __ldg(sp + i11);
                    float r0 = v00 * lyB.x + v10 * lyB.y;
                    float r1 = v01 * lyB.x + v11 * lyB.y;
                    float samp = r0 * wxv0 + r1 * wxv1;
                    C[1][c][k] = fmaf(f, samp, C[1][c][k]);
                }
                T[1][k] *= (1.0f - m);
            }
        }
    }

    // out = C + T*bg; load bg only where some transmittance remains
#pragma unroll
    for (int k = 0; k < 2; ++k) {
#pragma unroll
        for (int c = 0; c < CCH; ++c) {
            float o0 = C[0][c][k];
            float o1 = C[1][c][k];
            if (T[0][k] != 0.0f)
                o0 = fmaf(T[0][k], __ldg(bg + c * plane + off0 + (k << 8)), o0);
            if (T[1][k] != 0.0f)
                o1 = fmaf(T[1][k], __ldg(bg + c * plane + off1 + (k << 8)), o1);
            out[c * plane + off0 + (k << 8)] = o0;
            out[c * plane + off1 + (k << 8)] = o1;
        }
    }
}

extern "C" void kernel_launch(void* const* d_in, const int* in_sizes, int n_in,
                              void* d_out, int out_size) {
    const float* src  = (const float*)d_in[0];   // src_img [8,3,512,512]
    const float* bg   = (const float*)d_in[1];   // bg_img  [1,3,2048,2048]
    const float* coor = (const float*)d_in[2];   // coor    [8,4]
    float*       out  = (float*)d_out;           // [1,3,2048,2048]

    // LUT prep: 2048 indices × 8 layers
    prep_kernel<<<dim3(WO_ / 256, NIMG, 1), 256>>>(coor);

    // Composite: 4 blocks of 256 threads per row-pair; 1024 row-pairs
    dim3 grid(WO_ / 512, HO_ / 2, 1);
    composite_kernel<<<grid, 256>>>(src, bg, out);
}